// round 2
// baseline (speedup 1.0000x reference)
#include <cuda_runtime.h>
#include <cuda_bf16.h>
#include <math.h>

// Problem shape (fixed by dataset): N=500000, D=128, K=2048
#define MAXN   500000
#define DIM    128
#define NBINS  65536
#define CAP    4096
#define SORTN  4096
#define MAXK   2048
#define ROWS_PER_WARP 8

static __device__ unsigned int        g_keys[MAXN];
static __device__ unsigned int        g_hist[NBINS];
static __device__ unsigned int        g_counter;
static __device__ unsigned int        g_thresh;
static __device__ unsigned long long  g_cand[CAP];
static __device__ unsigned long long  g_topk[MAXK];

// order-preserving float -> u32 key
__device__ __forceinline__ unsigned int fkey(float f) {
    unsigned int b = __float_as_uint(f);
    return (b & 0x80000000u) ? ~b : (b | 0x80000000u);
}
__device__ __forceinline__ float fdec(unsigned int k) {
    unsigned int b = (k & 0x80000000u) ? (k ^ 0x80000000u) : ~k;
    return __uint_as_float(b);
}

// ---------------------------------------------------------------- kernel 1
__global__ void zero_kernel() {
    int i = blockIdx.x * blockDim.x + threadIdx.x;   // <<<64,256>>> threads, uint4 stores
    reinterpret_cast<uint4*>(g_hist)[i] = make_uint4(0u, 0u, 0u, 0u);
    if (i == 0) g_counter = 0u;
}

// ---------------------------------------------------------------- kernel 2
// persistent warps; each warp scores 8 rows per iteration (MLP=8)
__global__ void score_kernel(const float* __restrict__ x,
                             const float* __restrict__ p, int n) {
    const int lane   = threadIdx.x & 31;
    const int wid    = (blockIdx.x * blockDim.x + threadIdx.x) >> 5;
    const int nwarps = (gridDim.x * blockDim.x) >> 5;

    // ||p|| once per warp
    float4 p4 = reinterpret_cast<const float4*>(p)[lane];
    float sq = p4.x * p4.x + p4.y * p4.y + p4.z * p4.z + p4.w * p4.w;
    #pragma unroll
    for (int off = 16; off > 0; off >>= 1)
        sq += __shfl_xor_sync(0xFFFFFFFFu, sq, off);
    const float inv = rsqrtf(sq);

    const float4* __restrict__ x4p = reinterpret_cast<const float4*>(x);

    for (long long base = (long long)wid * ROWS_PER_WARP; base < n;
         base += (long long)nwarps * ROWS_PER_WARP) {

        float d[ROWS_PER_WARP];
        // 8 independent loads issued back-to-back -> MLP=8
        float4 v[ROWS_PER_WARP];
        #pragma unroll
        for (int r = 0; r < ROWS_PER_WARP; r++) {
            long long row = base + r;
            v[r] = (row < n) ? x4p[row * 32 + lane] : make_float4(0.f,0.f,0.f,0.f);
        }
        #pragma unroll
        for (int r = 0; r < ROWS_PER_WARP; r++) {
            d[r] = fmaf(v[r].x, p4.x, fmaf(v[r].y, p4.y,
                   fmaf(v[r].z, p4.z, v[r].w * p4.w)));
        }
        // 8 interleaved butterfly reductions (independent dep chains)
        #pragma unroll
        for (int off = 16; off > 0; off >>= 1) {
            #pragma unroll
            for (int r = 0; r < ROWS_PER_WARP; r++)
                d[r] += __shfl_xor_sync(0xFFFFFFFFu, d[r], off);
        }
        // lanes 0..7 each publish one row (parallel stores + atomics)
        if (lane < ROWS_PER_WARP) {
            long long row = base + lane;
            if (row < n) {
                unsigned int key = fkey(d[lane] * inv);
                g_keys[row] = key;
                atomicAdd(&g_hist[key >> 16], 1u);
            }
        }
    }
}

// ---------------------------------------------------------------- kernel 3
__global__ void thresh_kernel(int kk) {
    __shared__ unsigned int csum[256];
    __shared__ unsigned int cbin[256];
    __shared__ int schunk;
    __shared__ unsigned int sabove;
    int t = threadIdx.x;

    unsigned int s = 0;
    #pragma unroll 8
    for (int i = 0; i < 256; i++) s += g_hist[t * 256 + i];
    csum[t] = s;
    __syncthreads();

    if (t == 0) {
        unsigned int cum = 0; int ch = 0; sabove = 0;
        for (int c = 255; c >= 0; c--) {
            unsigned int nc = cum + csum[c];
            if (nc >= (unsigned int)kk) { ch = c; sabove = cum; break; }
            cum = nc;
        }
        schunk = ch;
    }
    __syncthreads();

    int ch = schunk;
    cbin[t] = g_hist[ch * 256 + t];
    __syncthreads();

    if (t == 0) {
        unsigned int cum = sabove;
        int b = ch * 256;
        for (int i = 255; i >= 0; i--) {
            cum += cbin[i];
            if (cum >= (unsigned int)kk) { b = ch * 256 + i; break; }
        }
        g_thresh = ((unsigned int)b) << 16;
    }
}

// ---------------------------------------------------------------- kernel 4
// grid-stride uint4 scan of keys (N divisible by 4)
__global__ void compact_kernel(int n) {
    const unsigned int thr = g_thresh;
    const int n4 = n >> 2;
    const int stride = gridDim.x * blockDim.x;
    const uint4* __restrict__ k4 = reinterpret_cast<const uint4*>(g_keys);

    for (int i = blockIdx.x * blockDim.x + threadIdx.x; i < n4; i += stride) {
        uint4 k = k4[i];
        unsigned int bi = (unsigned int)(i << 2);
        if (k.x >= thr) {
            unsigned int pos = atomicAdd(&g_counter, 1u);
            if (pos < CAP) g_cand[pos] = ((unsigned long long)k.x << 32) |
                                         (0xFFFFFFFFull - (bi + 0));
        }
        if (k.y >= thr) {
            unsigned int pos = atomicAdd(&g_counter, 1u);
            if (pos < CAP) g_cand[pos] = ((unsigned long long)k.y << 32) |
                                         (0xFFFFFFFFull - (bi + 1));
        }
        if (k.z >= thr) {
            unsigned int pos = atomicAdd(&g_counter, 1u);
            if (pos < CAP) g_cand[pos] = ((unsigned long long)k.z << 32) |
                                         (0xFFFFFFFFull - (bi + 2));
        }
        if (k.w >= thr) {
            unsigned int pos = atomicAdd(&g_counter, 1u);
            if (pos < CAP) g_cand[pos] = ((unsigned long long)k.w << 32) |
                                         (0xFFFFFFFFull - (bi + 3));
        }
    }
}

// ---------------------------------------------------------------- kernel 5
// single-block bitonic sort, descending, 4096 u64 in shared
__global__ void sort_kernel(int kk) {
    __shared__ unsigned long long s[SORTN];
    int tid = threadIdx.x;                       // 1024 threads
    unsigned int C = g_counter; if (C > CAP) C = CAP;

    #pragma unroll
    for (int i = tid; i < SORTN; i += 1024)
        s[i] = (i < (int)C) ? g_cand[i] : 0ULL;
    __syncthreads();

    for (int ks = 2; ks <= SORTN; ks <<= 1) {
        for (int j = ks >> 1; j > 0; j >>= 1) {
            #pragma unroll
            for (int i = tid; i < SORTN; i += 1024) {
                int l = i ^ j;
                if (l > i) {
                    unsigned long long a = s[i], b = s[l];
                    bool desc = ((i & ks) == 0);
                    bool sw = desc ? (a < b) : (a > b);
                    if (sw) { s[i] = b; s[l] = a; }
                }
            }
            __syncthreads();
        }
    }
    for (int i = tid; i < kk; i += 1024) g_topk[i] = s[i];
}

// ---------------------------------------------------------------- kernel 6
// warp-per-row gather with float4: out[j] = x[idx_j] * tanh(y_j)
__global__ void gather_kernel(const float* __restrict__ x,
                              float* __restrict__ out, int kk) {
    int lane = threadIdx.x & 31;
    int w    = (blockIdx.x * blockDim.x + threadIdx.x) >> 5;
    if (w >= kk) return;

    unsigned long long e = g_topk[w];
    unsigned int key = (unsigned int)(e >> 32);
    unsigned int idx = 0xFFFFFFFFu - (unsigned int)(e & 0xFFFFFFFFull);
    float tv = tanhf(fdec(key));

    const float4* __restrict__ src = reinterpret_cast<const float4*>(x) +
                                     (size_t)idx * 32;
    float4* __restrict__ dst = reinterpret_cast<float4*>(out) + (size_t)w * 32;
    float4 v = src[lane];
    v.x *= tv; v.y *= tv; v.z *= tv; v.w *= tv;
    dst[lane] = v;
}

// ----------------------------------------------------------------
extern "C" void kernel_launch(void* const* d_in, const int* in_sizes, int n_in,
                              void* d_out, int out_size) {
    const float* x = (const float*)d_in[0];
    const float* p = (const float*)d_in[1];
    float* out = (float*)d_out;

    int n  = in_sizes[0] / DIM;      // 500000
    int kk = out_size / DIM;         // 2048

    zero_kernel<<<64, 256>>>();                       // 65536 uints via uint4
    score_kernel<<<148 * 8, 256>>>(x, p, n);          // persistent, 8 rows/warp
    thresh_kernel<<<1, 256>>>(kk);
    compact_kernel<<<148 * 4, 256>>>(n);
    sort_kernel<<<1, 1024>>>(kk);
    gather_kernel<<<(kk * 32 + 255) / 256, 256>>>(x, out, kk);
}

// round 3
// speedup vs baseline: 1.6180x; 1.6180x over previous
#include <cuda_runtime.h>
#include <cuda_bf16.h>
#include <math.h>

// Problem shape (fixed by dataset): N=500000, D=128, K=2048
#define MAXN   500000
#define DIM    128
#define NBINS  65536
#define CAP    6144
#define MAXK   2048
#define ROWS_PER_WARP 8

static __device__ unsigned int        g_keys[MAXN];
static __device__ unsigned int        g_hist[NBINS];
static __device__ unsigned int        g_coarse[256];
static __device__ unsigned int        g_counter;
static __device__ unsigned int        g_thresh;
static __device__ unsigned long long  g_cand[CAP];
static __device__ unsigned long long  g_topk[MAXK];

// order-preserving float -> u32 key
__device__ __forceinline__ unsigned int fkey(float f) {
    unsigned int b = __float_as_uint(f);
    return (b & 0x80000000u) ? ~b : (b | 0x80000000u);
}
__device__ __forceinline__ float fdec(unsigned int k) {
    unsigned int b = (k & 0x80000000u) ? (k ^ 0x80000000u) : ~k;
    return __uint_as_float(b);
}

// ---------------------------------------------------------------- kernel 1
__global__ void zero_kernel() {
    int i = blockIdx.x * blockDim.x + threadIdx.x;   // <<<64,256>>>
    reinterpret_cast<uint4*>(g_hist)[i] = make_uint4(0u, 0u, 0u, 0u);
    if (i == 0) g_counter = 0u;
}

// ---------------------------------------------------------------- kernel 2
// persistent warps; each warp scores 8 rows per iteration
__global__ void score_kernel(const float* __restrict__ x,
                             const float* __restrict__ p, int n) {
    const int lane   = threadIdx.x & 31;
    const int wid    = (blockIdx.x * blockDim.x + threadIdx.x) >> 5;
    const int nwarps = (gridDim.x * blockDim.x) >> 5;

    float4 p4 = reinterpret_cast<const float4*>(p)[lane];
    float sq = p4.x * p4.x + p4.y * p4.y + p4.z * p4.z + p4.w * p4.w;
    #pragma unroll
    for (int off = 16; off > 0; off >>= 1)
        sq += __shfl_xor_sync(0xFFFFFFFFu, sq, off);
    const float inv = rsqrtf(sq);

    const float4* __restrict__ x4p = reinterpret_cast<const float4*>(x);

    for (long long base = (long long)wid * ROWS_PER_WARP; base < n;
         base += (long long)nwarps * ROWS_PER_WARP) {

        float d[ROWS_PER_WARP];
        float4 v[ROWS_PER_WARP];
        #pragma unroll
        for (int r = 0; r < ROWS_PER_WARP; r++) {
            long long row = base + r;
            v[r] = (row < n) ? x4p[row * 32 + lane] : make_float4(0.f,0.f,0.f,0.f);
        }
        #pragma unroll
        for (int r = 0; r < ROWS_PER_WARP; r++) {
            d[r] = fmaf(v[r].x, p4.x, fmaf(v[r].y, p4.y,
                   fmaf(v[r].z, p4.z, v[r].w * p4.w)));
        }
        #pragma unroll
        for (int off = 16; off > 0; off >>= 1) {
            #pragma unroll
            for (int r = 0; r < ROWS_PER_WARP; r++)
                d[r] += __shfl_xor_sync(0xFFFFFFFFu, d[r], off);
        }
        if (lane < ROWS_PER_WARP) {
            long long row = base + lane;
            if (row < n) {
                unsigned int key = fkey(d[lane] * inv);
                g_keys[row] = key;
                atomicAdd(&g_hist[key >> 16], 1u);
            }
        }
    }
}

// ---------------------------------------------------------------- kernel 3
// coarse sums: g_coarse[b] = sum of g_hist[b*256 .. b*256+255]; <<<256,256>>>
__global__ void coarse_kernel() {
    __shared__ unsigned int s[256];
    int t = threadIdx.x;
    s[t] = g_hist[blockIdx.x * 256 + t];
    __syncthreads();
    // tree reduce
    for (int off = 128; off >= 32; off >>= 1) {
        if (t < off) s[t] += s[t + off];
        __syncthreads();
    }
    if (t < 32) {
        unsigned int v = s[t];
        #pragma unroll
        for (int off = 16; off > 0; off >>= 1)
            v += __shfl_xor_sync(0xFFFFFFFFu, v, off);
        if (t == 0) g_coarse[blockIdx.x] = v;
    }
}

// ---------------------------------------------------------------- kernel 4
// find smallest bin b with count(key >= b<<16) >= kk; <<<1,256>>>
__global__ void thresh_kernel(int kk) {
    __shared__ unsigned int cs[256];
    __shared__ int schunk;
    __shared__ unsigned int sabove;
    int t = threadIdx.x;

    cs[t] = g_coarse[t];
    __syncthreads();

    if (t == 0) {
        unsigned int cum = 0; int ch = 0; unsigned int ab = 0;
        for (int c = 255; c >= 0; c--) {
            unsigned int nc = cum + cs[c];
            if (nc >= (unsigned int)kk) { ch = c; ab = cum; break; }
            cum = nc;
        }
        schunk = ch; sabove = ab;
    }
    __syncthreads();

    int ch = schunk;
    cs[t] = g_hist[ch * 256 + t];
    __syncthreads();

    if (t == 0) {
        unsigned int cum = sabove;
        int b = ch * 256;
        for (int i = 255; i >= 0; i--) {
            cum += cs[i];
            if (cum >= (unsigned int)kk) { b = ch * 256 + i; break; }
        }
        g_thresh = ((unsigned int)b) << 16;
    }
}

// ---------------------------------------------------------------- kernel 5
// grid-stride uint4 scan of keys
__global__ void compact_kernel(int n) {
    const unsigned int thr = g_thresh;
    const int n4 = n >> 2;
    const int stride = gridDim.x * blockDim.x;
    const uint4* __restrict__ k4 = reinterpret_cast<const uint4*>(g_keys);

    for (int i = blockIdx.x * blockDim.x + threadIdx.x; i < n4; i += stride) {
        uint4 k = k4[i];
        unsigned int bi = (unsigned int)(i << 2);
        if (k.x >= thr) {
            unsigned int pos = atomicAdd(&g_counter, 1u);
            if (pos < CAP) g_cand[pos] = ((unsigned long long)k.x << 32) |
                                         (0xFFFFFFFFull - (bi + 0));
        }
        if (k.y >= thr) {
            unsigned int pos = atomicAdd(&g_counter, 1u);
            if (pos < CAP) g_cand[pos] = ((unsigned long long)k.y << 32) |
                                         (0xFFFFFFFFull - (bi + 1));
        }
        if (k.z >= thr) {
            unsigned int pos = atomicAdd(&g_counter, 1u);
            if (pos < CAP) g_cand[pos] = ((unsigned long long)k.z << 32) |
                                         (0xFFFFFFFFull - (bi + 2));
        }
        if (k.w >= thr) {
            unsigned int pos = atomicAdd(&g_counter, 1u);
            if (pos < CAP) g_cand[pos] = ((unsigned long long)k.w << 32) |
                                         (0xFFFFFFFFull - (bi + 3));
        }
    }
}

// ---------------------------------------------------------------- kernel 6
// rank by counting: warp per candidate; scatter into g_topk[rank]
// total order is tie-free (idx embedded), so ranks are unique.
__global__ void rank_kernel(int kk) {
    unsigned int C = g_counter; if (C > CAP) C = CAP;
    int w    = (blockIdx.x * blockDim.x + threadIdx.x) >> 5;
    int lane = threadIdx.x & 31;
    if (w >= (int)C) return;

    unsigned long long me = g_cand[w];
    int cnt = 0;
    int j = lane;
    // unrolled-by-4 stride loop for MLP
    for (; j + 96 < (int)C; j += 128) {
        unsigned long long a = g_cand[j];
        unsigned long long b = g_cand[j + 32];
        unsigned long long c = g_cand[j + 64];
        unsigned long long d = g_cand[j + 96];
        cnt += (a > me) + (b > me) + (c > me) + (d > me);
    }
    for (; j < (int)C; j += 32)
        cnt += (g_cand[j] > me);

    #pragma unroll
    for (int off = 16; off > 0; off >>= 1)
        cnt += __shfl_xor_sync(0xFFFFFFFFu, cnt, off);

    if (lane == 0 && cnt < kk) g_topk[cnt] = me;
}

// ---------------------------------------------------------------- kernel 7
// warp-per-row gather: out[j] = x[idx_j] * tanh(y_j)
__global__ void gather_kernel(const float* __restrict__ x,
                              float* __restrict__ out, int kk) {
    int lane = threadIdx.x & 31;
    int w    = (blockIdx.x * blockDim.x + threadIdx.x) >> 5;
    if (w >= kk) return;

    unsigned long long e = g_topk[w];
    unsigned int key = (unsigned int)(e >> 32);
    unsigned int idx = 0xFFFFFFFFu - (unsigned int)(e & 0xFFFFFFFFull);
    float tv = tanhf(fdec(key));

    const float4* __restrict__ src = reinterpret_cast<const float4*>(x) +
                                     (size_t)idx * 32;
    float4* __restrict__ dst = reinterpret_cast<float4*>(out) + (size_t)w * 32;
    float4 v = src[lane];
    v.x *= tv; v.y *= tv; v.z *= tv; v.w *= tv;
    dst[lane] = v;
}

// ----------------------------------------------------------------
extern "C" void kernel_launch(void* const* d_in, const int* in_sizes, int n_in,
                              void* d_out, int out_size) {
    const float* x = (const float*)d_in[0];
    const float* p = (const float*)d_in[1];
    float* out = (float*)d_out;

    int n  = in_sizes[0] / DIM;      // 500000
    int kk = out_size / DIM;         // 2048

    zero_kernel<<<64, 256>>>();
    score_kernel<<<148 * 8, 256>>>(x, p, n);
    coarse_kernel<<<256, 256>>>();
    thresh_kernel<<<1, 256>>>(kk);
    compact_kernel<<<148 * 4, 256>>>(n);
    rank_kernel<<<(CAP * 32) / 256, 256>>>(kk);      // 6144 warps, guarded by C
    gather_kernel<<<(kk * 32 + 255) / 256, 256>>>(x, out, kk);
}

// round 4
// speedup vs baseline: 1.7552x; 1.0848x over previous
#include <cuda_runtime.h>
#include <cuda_bf16.h>
#include <math.h>

// Problem shape (fixed by dataset): N=500000, D=128, K=2048
#define MAXN   500000
#define DIM    128
#define NBINS  65536
#define CAP    6144
#define MAXK   2048
#define ROWS_PER_WARP 8

static __device__ unsigned int        g_keys[MAXN];
static __device__ unsigned int        g_hist[NBINS];
static __device__ unsigned int        g_coarse[256];
static __device__ unsigned int        g_counter;
static __device__ unsigned int        g_done;
static __device__ unsigned int        g_thresh;
static __device__ unsigned long long  g_cand[CAP];

// order-preserving float -> u32 key
__device__ __forceinline__ unsigned int fkey(float f) {
    unsigned int b = __float_as_uint(f);
    return (b & 0x80000000u) ? ~b : (b | 0x80000000u);
}
__device__ __forceinline__ float fdec(unsigned int k) {
    unsigned int b = (k & 0x80000000u) ? (k ^ 0x80000000u) : ~k;
    return __uint_as_float(b);
}

// ---------------------------------------------------------------- kernel 1
__global__ void zero_kernel() {
    int i = blockIdx.x * blockDim.x + threadIdx.x;   // <<<64,256>>>
    reinterpret_cast<uint4*>(g_hist)[i] = make_uint4(0u, 0u, 0u, 0u);
    if (i == 0) { g_counter = 0u; g_done = 0u; }
}

// ---------------------------------------------------------------- kernel 2
// persistent warps; each warp scores 8 rows per iteration (streaming loads)
__global__ void score_kernel(const float* __restrict__ x,
                             const float* __restrict__ p, int n) {
    const int lane   = threadIdx.x & 31;
    const int wid    = (blockIdx.x * blockDim.x + threadIdx.x) >> 5;
    const int nwarps = (gridDim.x * blockDim.x) >> 5;

    float4 p4 = reinterpret_cast<const float4*>(p)[lane];
    float sq = p4.x * p4.x + p4.y * p4.y + p4.z * p4.z + p4.w * p4.w;
    #pragma unroll
    for (int off = 16; off > 0; off >>= 1)
        sq += __shfl_xor_sync(0xFFFFFFFFu, sq, off);
    const float inv = rsqrtf(sq);

    const float4* __restrict__ x4p = reinterpret_cast<const float4*>(x);

    for (long long base = (long long)wid * ROWS_PER_WARP; base < n;
         base += (long long)nwarps * ROWS_PER_WARP) {

        float d[ROWS_PER_WARP];
        float4 v[ROWS_PER_WARP];
        #pragma unroll
        for (int r = 0; r < ROWS_PER_WARP; r++) {
            long long row = base + r;
            v[r] = (row < n) ? __ldcs(&x4p[row * 32 + lane])
                             : make_float4(0.f, 0.f, 0.f, 0.f);
        }
        #pragma unroll
        for (int r = 0; r < ROWS_PER_WARP; r++) {
            d[r] = fmaf(v[r].x, p4.x, fmaf(v[r].y, p4.y,
                   fmaf(v[r].z, p4.z, v[r].w * p4.w)));
        }
        #pragma unroll
        for (int off = 16; off > 0; off >>= 1) {
            #pragma unroll
            for (int r = 0; r < ROWS_PER_WARP; r++)
                d[r] += __shfl_xor_sync(0xFFFFFFFFu, d[r], off);
        }
        if (lane < ROWS_PER_WARP) {
            long long row = base + lane;
            if (row < n) {
                unsigned int key = fkey(d[lane] * inv);
                __stcs(&g_keys[row], key);
                atomicAdd(&g_hist[key >> 16], 1u);
            }
        }
    }
}

// ---------------------------------------------------------------- kernel 3
// fused coarse sums + threshold search (last-block-done pattern); <<<256,256>>>
__global__ void coarse_thresh_kernel(int kk) {
    __shared__ unsigned int sh[256];
    __shared__ unsigned int suf[256];
    __shared__ int s_last;
    __shared__ int s_ch;
    __shared__ unsigned int s_above;

    int t = threadIdx.x;
    int b = blockIdx.x;

    // ---- phase 1: per-block coarse sum of hist chunk b ----
    sh[t] = g_hist[b * 256 + t];
    __syncthreads();
    #pragma unroll
    for (int off = 128; off >= 1; off >>= 1) {
        if (t < off) sh[t] += sh[t + off];
        __syncthreads();
    }
    if (t == 0) {
        g_coarse[b] = sh[0];
        __threadfence();
        unsigned int d = atomicAdd(&g_done, 1u);
        s_last = (d == 255u);
    }
    __syncthreads();
    if (!s_last) return;

    // ---- phase 2 (last block only): threshold search ----
    __threadfence();
    // suffix scan over coarse chunks
    suf[t] = g_coarse[t];
    __syncthreads();
    #pragma unroll
    for (int off = 1; off < 256; off <<= 1) {
        unsigned int u = (t + off < 256) ? suf[t + off] : 0u;
        __syncthreads();
        suf[t] += u;
        __syncthreads();
    }
    // chunk = largest t with suffix >= kk (unique crossing point)
    if (suf[t] >= (unsigned int)kk &&
        (t == 255 || suf[t + 1] < (unsigned int)kk)) {
        s_ch = t;
        s_above = (t == 255) ? 0u : suf[t + 1];
    }
    __syncthreads();

    int ch = s_ch;
    unsigned int above = s_above;

    // suffix scan over fine bins of the crossing chunk
    sh[t] = g_hist[ch * 256 + t];
    __syncthreads();
    #pragma unroll
    for (int off = 1; off < 256; off <<= 1) {
        unsigned int u = (t + off < 256) ? sh[t + off] : 0u;
        __syncthreads();
        sh[t] += u;
        __syncthreads();
    }
    if (above + sh[t] >= (unsigned int)kk &&
        (t == 255 || above + sh[t + 1] < (unsigned int)kk)) {
        g_thresh = ((unsigned int)(ch * 256 + t)) << 16;
    }
}

// ---------------------------------------------------------------- kernel 4
// compact: 16 keys per thread via 4 independent uint4 loads (MLP=4)
__global__ void compact_kernel(int n) {
    const unsigned int thr = g_thresh;
    const int n16 = (n + 15) >> 4;               // threads needed
    int i = blockIdx.x * blockDim.x + threadIdx.x;
    if (i >= n16) return;

    const uint4* __restrict__ k4 = reinterpret_cast<const uint4*>(g_keys);
    int q0 = i * 4;                              // first uint4 index
    int nq = n >> 2;                             // total uint4s (n % 4 == 0)

    uint4 k[4];
    #pragma unroll
    for (int j = 0; j < 4; j++)
        k[j] = (q0 + j < nq) ? __ldcs(&k4[q0 + j]) : make_uint4(0u,0u,0u,0u);

    #pragma unroll
    for (int j = 0; j < 4; j++) {
        unsigned int bi = (unsigned int)((q0 + j) << 2);
        unsigned int kv[4] = {k[j].x, k[j].y, k[j].z, k[j].w};
        #pragma unroll
        for (int e = 0; e < 4; e++) {
            if (kv[e] >= thr) {
                unsigned int pos = atomicAdd(&g_counter, 1u);
                if (pos < CAP)
                    g_cand[pos] = ((unsigned long long)kv[e] << 32) |
                                  (0xFFFFFFFFull - (bi + e));
            }
        }
    }
}

// ---------------------------------------------------------------- kernel 5
// fused rank-by-counting + gather: warp per candidate; writes out[rank] row
__global__ void rank_gather_kernel(const float* __restrict__ x,
                                   float* __restrict__ out, int kk) {
    unsigned int C = g_counter; if (C > CAP) C = CAP;
    int w    = (blockIdx.x * blockDim.x + threadIdx.x) >> 5;
    int lane = threadIdx.x & 31;
    if (w >= (int)C) return;

    unsigned long long me = g_cand[w];
    int cnt = 0;
    int j = lane;
    for (; j + 96 < (int)C; j += 128) {
        unsigned long long a = g_cand[j];
        unsigned long long b = g_cand[j + 32];
        unsigned long long c = g_cand[j + 64];
        unsigned long long d = g_cand[j + 96];
        cnt += (a > me) + (b > me) + (c > me) + (d > me);
    }
    for (; j < (int)C; j += 32)
        cnt += (g_cand[j] > me);

    #pragma unroll
    for (int off = 16; off > 0; off >>= 1)
        cnt += __shfl_xor_sync(0xFFFFFFFFu, cnt, off);   // all lanes get rank

    if (cnt < kk) {
        unsigned int key = (unsigned int)(me >> 32);
        unsigned int idx = 0xFFFFFFFFu - (unsigned int)(me & 0xFFFFFFFFull);
        float tv = tanhf(fdec(key));
        const float4* __restrict__ src = reinterpret_cast<const float4*>(x) +
                                         (size_t)idx * 32;
        float4* __restrict__ dst = reinterpret_cast<float4*>(out) +
                                   (size_t)cnt * 32;
        float4 v = src[lane];
        v.x *= tv; v.y *= tv; v.z *= tv; v.w *= tv;
        dst[lane] = v;
    }
}

// ----------------------------------------------------------------
extern "C" void kernel_launch(void* const* d_in, const int* in_sizes, int n_in,
                              void* d_out, int out_size) {
    const float* x = (const float*)d_in[0];
    const float* p = (const float*)d_in[1];
    float* out = (float*)d_out;

    int n  = in_sizes[0] / DIM;      // 500000
    int kk = out_size / DIM;         // 2048

    zero_kernel<<<64, 256>>>();
    score_kernel<<<148 * 8, 256>>>(x, p, n);
    coarse_thresh_kernel<<<256, 256>>>(kk);
    int n16 = (n + 15) >> 4;
    compact_kernel<<<(n16 + 255) / 256, 256>>>(n);
    rank_gather_kernel<<<(CAP * 32) / 256, 256>>>(x, out, kk);
}